// round 15
// baseline (speedup 1.0000x reference)
#include <cuda_runtime.h>
#include <cuda_fp16.h>
#include <math.h>
#include <stdint.h>

// ---------------------------------------------------------------------------
// Problem constants
// ---------------------------------------------------------------------------
#define B_  2
#define T_  2048
#define E_  1024
#define H_  16
#define D_  64
#define M_  (B_ * T_)          // 4096
#define QKV_N (3 * E_)         // 3072
#define FC_N  (4 * E_)         // 4096

// ---------------------------------------------------------------------------
// Scratch (device globals; allocations forbidden)
// ---------------------------------------------------------------------------
__device__ __half g_lnH  [(size_t)M_ * E_];
__device__ __half g_qkvH [(size_t)M_ * QKV_N];
__device__ __half g_attnH[(size_t)M_ * E_];
__device__ float  g_x1   [(size_t)M_ * E_];
__device__ __half g_fcH  [(size_t)M_ * FC_N];
__device__ uint32_t g_wqkvP [(size_t)QKV_N * E_ / 2];
__device__ uint32_t g_woP   [(size_t)E_ * E_ / 2];
__device__ uint32_t g_wfcP  [(size_t)FC_N * E_ / 2];
__device__ uint32_t g_wprojP[(size_t)E_ * FC_N / 2];

// ---------------------------------------------------------------------------
// Helpers
// ---------------------------------------------------------------------------
__device__ __forceinline__ uint32_t smem_u32(const void* p) {
    uint32_t a;
    asm("{ .reg .u64 t; cvta.to.shared.u64 t, %1; cvt.u32.u64 %0, t; }" : "=r"(a) : "l"(p));
    return a;
}
#define CP_ASYNC16(dst, src) \
    asm volatile("cp.async.cg.shared.global [%0], [%1], 16;" :: "r"(dst), "l"(src) : "memory")
#define CP_COMMIT() asm volatile("cp.async.commit_group;" ::: "memory")

__device__ __forceinline__ void ldsm_x4(uint32_t (&r)[4], uint32_t addr) {
    asm volatile("ldmatrix.sync.aligned.m8n8.x4.shared.b16 {%0,%1,%2,%3}, [%4];"
                 : "=r"(r[0]), "=r"(r[1]), "=r"(r[2]), "=r"(r[3]) : "r"(addr));
}
__device__ __forceinline__ void ldsm_x4_trans(uint32_t (&r)[4], uint32_t addr) {
    asm volatile("ldmatrix.sync.aligned.m8n8.x4.trans.shared.b16 {%0,%1,%2,%3}, [%4];"
                 : "=r"(r[0]), "=r"(r[1]), "=r"(r[2]), "=r"(r[3]) : "r"(addr));
}

// fp16 MMA: m16n8k16, fp32 accumulate
__device__ __forceinline__ void mma_f16(float (&c)[4],
                                        uint32_t a0, uint32_t a1, uint32_t a2, uint32_t a3,
                                        uint32_t b0, uint32_t b1) {
    asm volatile(
        "mma.sync.aligned.m16n8k16.row.col.f32.f16.f16.f32 "
        "{%0,%1,%2,%3}, {%4,%5,%6,%7}, {%8,%9}, {%0,%1,%2,%3};"
        : "+f"(c[0]), "+f"(c[1]), "+f"(c[2]), "+f"(c[3])
        : "r"(a0), "r"(a1), "r"(a2), "r"(a3), "r"(b0), "r"(b1));
}
__device__ __forceinline__ uint32_t pack_h2(float lo, float hi) {
    const __half2 h = __floats2half2_rn(lo, hi);
    return *(const uint32_t*)&h;
}

// ---------------------------------------------------------------------------
// Merged weight pack (unchanged)
// ---------------------------------------------------------------------------
__global__ void pack_all_kernel(const float* __restrict__ W0, uint32_t* __restrict__ P0,
                                const float* __restrict__ W1, uint32_t* __restrict__ P1,
                                const float* __restrict__ W2, uint32_t* __restrict__ P2,
                                const float* __restrict__ W3, uint32_t* __restrict__ P3)
{
    __shared__ float ws[32][132];
    const int bid = blockIdx.x;
    const int tid = threadIdx.x;               // 256

    const float* W; uint32_t* Wp; int N, ntx, nkt, r;
    if (bid < 768)       { W = W0; Wp = P0; N = QKV_N; ntx = 24; nkt = 32;  r = bid; }
    else if (bid < 1024) { W = W1; Wp = P1; N = E_;    ntx = 8;  nkt = 32;  r = bid - 768; }
    else if (bid < 2048) { W = W2; Wp = P2; N = FC_N;  ntx = 32; nkt = 32;  r = bid - 1024; }
    else                 { W = W3; Wp = P3; N = E_;    ntx = 8;  nkt = 128; r = bid - 2048; }
    const int nt = r % ntx;
    const int kt = r / ntx;

    const float* src = W + (size_t)(kt * 32) * N + nt * 128;
    #pragma unroll
    for (int i = 0; i < 4; i++) {
        const int idx = tid + i * 256;
        const int rr = idx >> 5, c4 = idx & 31;
        *(float4*)&ws[rr][c4 * 4] = *(const float4*)(src + (size_t)rr * N + c4 * 4);
    }
    __syncthreads();

    uint32_t* dst = Wp + ((size_t)nt * nkt + kt) * 2048;
    #pragma unroll
    for (int i = 0; i < 8; i++) {
        const int o = tid + i * 256;
        const int s = o >> 6;
        const int lane = (o >> 1) & 31;
        const int reg = o & 1;
        const int kbb = s >> 4, nb = s & 15;
        const int g = lane >> 2, tig = lane & 3;
        const int k = kbb * 16 + reg * 8 + 2 * tig;
        const int n = nb * 8 + g;
        dst[o] = pack_h2(ws[k][n], ws[k + 1][n]);
    }
}

// ---------------------------------------------------------------------------
// fp16 mma.sync GEMM: BM=BN=128, BK=64 per stage, 3-stage cp.async pipeline.
// (Round-14 champion config — unchanged.)
// EPI: 0=bias (fp32 C), 1=bias+res (fp32 C), 2=bias+GELU (half C), 3=bias (half C)
// ---------------------------------------------------------------------------
#define SA_STR_H   72
#define SA_H_BYTES (128 * SA_STR_H * 2)      // 18432
#define SB_H_BYTES 16384
#define BUF_H      (SA_H_BYTES + SB_H_BYTES) // 34816
#define GEMM_H_SMEM (3 * BUF_H)              // 104448

template<int EPI>
__global__ void __launch_bounds__(128, 2)
gemm_h_kernel(const __half* __restrict__ A, const uint32_t* __restrict__ Wp,
              const float* __restrict__ bias, const float* __restrict__ res,
              void* __restrict__ Cv, int N, int K)
{
    extern __shared__ char smem[];
    const uint32_t sbase = smem_u32(smem);
    float* Cf = (float*)Cv;
    __half* Ch = (__half*)Cv;

    const int tid  = threadIdx.x;
    const int wid  = tid >> 5;
    const int lane = tid & 31;
    const int g    = lane >> 2;
    const int tig  = lane & 3;
    const int wm   = (wid >> 1) * 64;
    const int wn   = (wid & 1) * 64;
    const int m0   = blockIdx.y * 128;
    const int n0   = blockIdx.x * 128;

    const int ntile = K >> 6;
    const size_t wtile0 = (size_t)blockIdx.x * (K >> 5) * 2048;

    const int am = tid >> 3;
    const int ac = tid & 7;

    const int arow = lane & 15;
    const int acol = (lane >> 4) * 8;

    float acc[4][8][4];
    #pragma unroll
    for (int mt = 0; mt < 4; mt++)
        #pragma unroll
        for (int nb = 0; nb < 8; nb++)
            #pragma unroll
            for (int r = 0; r < 4; r++) acc[mt][nb][r] = 0.f;

    auto load_tile = [&](int buf, int kt) {
        const uint32_t sA = sbase + buf * BUF_H;
        const uint32_t sB = sA + SA_H_BYTES;
        const __half* asrc = A + (size_t)(m0 + am) * K + kt * 64 + ac * 8;
        #pragma unroll
        for (int i = 0; i < 8; i++) {
            CP_ASYNC16(sA + (uint32_t)(am + i * 16) * (SA_STR_H * 2) + ac * 16,
                       asrc + (size_t)i * 16 * K);
        }
        const uint32_t* bsrc = Wp + wtile0 + (size_t)kt * 4096 + tid * 4;
        #pragma unroll
        for (int i = 0; i < 8; i++) {
            CP_ASYNC16(sB + (uint32_t)(tid + i * 128) * 16, bsrc + i * 512);
        }
        CP_COMMIT();
    };

    load_tile(0, 0);
    if (ntile > 1) load_tile(1, 1);

    for (int t = 0; t < ntile; t++) {
        if (t + 1 < ntile) {
            asm volatile("cp.async.wait_group 1;" ::: "memory");
        } else {
            asm volatile("cp.async.wait_group 0;" ::: "memory");
        }
        __syncthreads();
        if (t + 2 < ntile) load_tile((t + 2) % 3, t + 2);

        const int cur = t % 3;
        const uint32_t sA = sbase + cur * BUF_H;
        const uint32_t* Bs = (const uint32_t*)(smem + cur * BUF_H + SA_H_BYTES);

        #pragma unroll
        for (int kbb = 0; kbb < 4; kbb++) {
            uint32_t a[4][4];
            #pragma unroll
            for (int mt = 0; mt < 4; mt++) {
                const uint32_t addr = sA +
                    (uint32_t)((wm + mt * 16 + arow) * SA_STR_H + kbb * 16 + acol) * 2;
                ldsm_x4(a[mt], addr);
            }
            const uint32_t* Bsub = Bs + (kbb >> 1) * 2048;
            #pragma unroll
            for (int nb = 0; nb < 8; nb++) {
                const int s = (kbb & 1) * 16 + (wn >> 3) + nb;
                const uint2 bb = *(const uint2*)(Bsub + s * 64 + lane * 2);
                #pragma unroll
                for (int mt = 0; mt < 4; mt++)
                    mma_f16(acc[mt][nb], a[mt][0], a[mt][1], a[mt][2], a[mt][3],
                            bb.x, bb.y);
            }
        }
    }

    #pragma unroll
    for (int mt = 0; mt < 4; mt++) {
        const size_t r0 = (size_t)(m0 + wm + mt * 16 + g);
        #pragma unroll
        for (int nb = 0; nb < 8; nb++) {
            const int col = n0 + wn + nb * 8 + 2 * tig;
            const float2 bv = *(const float2*)(bias + col);
            #pragma unroll
            for (int hh = 0; hh < 2; hh++) {
                const size_t row = r0 + hh * 8;
                float vx = acc[mt][nb][hh * 2 + 0] + bv.x;
                float vy = acc[mt][nb][hh * 2 + 1] + bv.y;
                if (EPI == 1) {
                    const float2 r2 = *(const float2*)(res + row * N + col);
                    vx += r2.x; vy += r2.y;
                }
                if (EPI == 2) {
                    vx = 0.5f * vx * (1.0f + erff(vx * 0.70710678118654752f));
                    vy = 0.5f * vy * (1.0f + erff(vy * 0.70710678118654752f));
                }
                if (EPI == 2 || EPI == 3) {
                    *(__half2*)(Ch + row * N + col) = __floats2half2_rn(vx, vy);
                } else {
                    float2 o2; o2.x = vx; o2.y = vy;
                    *(float2*)(Cf + row * N + col) = o2;
                }
            }
        }
    }
}

// ---------------------------------------------------------------------------
// LayerNorm: warp-per-row (unchanged)
// ---------------------------------------------------------------------------
__global__ void layernorm_kernel(const float* __restrict__ x,
                                 const float* __restrict__ gamma,
                                 const float* __restrict__ beta,
                                 __half* __restrict__ out)
{
    const int wid  = threadIdx.x >> 5;
    const int lane = threadIdx.x & 31;
    const int row  = blockIdx.x * 8 + wid;

    const float4* xr = (const float4*)(x + (size_t)row * E_);
    float4 v[8];
    float s = 0.f, ss = 0.f;
    #pragma unroll
    for (int i = 0; i < 8; i++) {
        v[i] = xr[lane + 32 * i];
        s  += (v[i].x + v[i].y) + (v[i].z + v[i].w);
        ss += (v[i].x * v[i].x + v[i].y * v[i].y) + (v[i].z * v[i].z + v[i].w * v[i].w);
    }
    #pragma unroll
    for (int o = 16; o > 0; o >>= 1) {
        s  += __shfl_xor_sync(0xffffffffu, s,  o);
        ss += __shfl_xor_sync(0xffffffffu, ss, o);
    }
    const float mean = s * (1.0f / E_);
    const float var  = ss * (1.0f / E_) - mean * mean;
    const float r    = rsqrtf(var + 1e-5f);

    const float4* gp = (const float4*)gamma;
    const float4* bp = (const float4*)beta;
    __half2* op = (__half2*)(out + (size_t)row * E_);
    #pragma unroll
    for (int i = 0; i < 8; i++) {
        const int c4 = lane + 32 * i;
        const float4 gv = gp[c4];
        const float4 bv = bp[c4];
        op[c4 * 2 + 0] = __floats2half2_rn((v[i].x - mean) * r * gv.x + bv.x,
                                           (v[i].y - mean) * r * gv.y + bv.y);
        op[c4 * 2 + 1] = __floats2half2_rn((v[i].z - mean) * r * gv.z + bv.z,
                                           (v[i].w - mean) * r * gv.w + bv.w);
    }
}

// ---------------------------------------------------------------------------
// Flash attention: 128-query blocks, 256 threads (8 warps x 16 queries),
// fp16 mma + ldmatrix + double-buffered 64-key K/V tiles.
// smem: Q[128][72] | stage0 K,V[64][72] | stage1 K,V[64][72]  = 55296 B
// ---------------------------------------------------------------------------
#define KVSTR 72
#define QBYTES (128 * KVSTR * 2)           // 18432
#define KVBYTES (64 * KVSTR * 2)           // 9216
#define ATT_SMEM (QBYTES + 4 * KVBYTES)    // 55296

__global__ void __launch_bounds__(256, 2)
attn_h_kernel(const __half* __restrict__ qkv, __half* __restrict__ out)
{
    extern __shared__ __half smh[];
    const uint32_t sQ = smem_u32(smh);

    const int bh  = blockIdx.y;
    const int b   = bh >> 4;
    const int h   = bh & 15;
    const int m0  = (gridDim.x - 1 - blockIdx.x) * 128;   // longest blocks first
    const int tid = threadIdx.x;
    const int wid = tid >> 5;                             // 0..7
    const int lane = tid & 31;
    const int g    = lane >> 2;
    const int tig  = lane & 3;
    const int qr   = wid * 16;                            // 0..112
    const int lq   = lane >> 3;
    const int lr   = lane & 7;
    const float NEG_INF = __int_as_float(0xff800000);

    // ---- stage Q tile (128 rows) + first K/V tile ----
    const size_t baseQ = ((size_t)(b * T_ + m0)) * QKV_N + h * D_;
    #pragma unroll
    for (int i = 0; i < 4; i++) {
        const int idx = tid + i * 256;       // 0..1023
        const int r = idx >> 3, c = idx & 7;
        CP_ASYNC16(sQ + (uint32_t)(r * KVSTR + c * 8) * 2,
                   qkv + baseQ + (size_t)r * QKV_N + c * 8);
    }
    CP_COMMIT();

    auto load_kv = [&](int stage, int t) {
        const uint32_t sK = sQ + QBYTES + (uint32_t)stage * 2 * KVBYTES;
        const uint32_t sV = sK + KVBYTES;
        const size_t baseK = ((size_t)(b * T_ + t * 64)) * QKV_N + E_ + h * D_;
        #pragma unroll
        for (int i = 0; i < 2; i++) {
            const int idx = tid + i * 256;   // 0..511
            const int r = idx >> 3, c = idx & 7;
            const __half* src = qkv + baseK + (size_t)r * QKV_N + c * 8;
            CP_ASYNC16(sK + (uint32_t)(r * KVSTR + c * 8) * 2, src);
            CP_ASYNC16(sV + (uint32_t)(r * KVSTR + c * 8) * 2, src + E_);
        }
        CP_COMMIT();
    };
    load_kv(0, 0);

    asm volatile("cp.async.wait_group 0;" ::: "memory");
    __syncthreads();

    // Q fragments, scaled by 2^-3 (exact in fp16)
    const __half2 qscale = __half2half2(__float2half_rn(0.125f));
    uint32_t qf[4][4];
    #pragma unroll
    for (int kc = 0; kc < 4; kc++) {
        const __half* Qp = smh;
        #pragma unroll
        for (int j = 0; j < 4; j++) {
            const int rr = qr + g + (j & 1) * 8;
            const int cc = kc * 16 + 2 * tig + (j >> 1) * 8;
            __half2 q2 = *(const __half2*)(Qp + rr * KVSTR + cc);
            q2 = __hmul2(q2, qscale);
            qf[kc][j] = *(const uint32_t*)&q2;
        }
    }

    float oacc[8][4];
    #pragma unroll
    for (int nb = 0; nb < 8; nb++)
        #pragma unroll
        for (int r = 0; r < 4; r++) oacc[nb][r] = 0.f;
    float mr0 = NEG_INF, mr1 = NEG_INF, l0 = 0.f, l1 = 0.f;

    const int tq0 = m0 + qr + g;
    const int tq1 = tq0 + 8;
    const int ntile = (m0 >> 6) + 2;       // key tiles 0 .. (m0+127)/64

    for (int t = 0; t < ntile; t++) {
        const int j0 = t * 64;
        const int cur = t & 1;
        if (t + 1 < ntile) {
            load_kv(cur ^ 1, t + 1);
            asm volatile("cp.async.wait_group 1;" ::: "memory");
        } else {
            asm volatile("cp.async.wait_group 0;" ::: "memory");
        }
        __syncthreads();

        const uint32_t sK = sQ + QBYTES + (uint32_t)cur * 2 * KVBYTES;
        const uint32_t sV = sK + KVBYTES;

        // ---- QK^T via ldmatrix K fragments ----
        float sc[8][4];
        #pragma unroll
        for (int jb = 0; jb < 8; jb++)
            sc[jb][0] = sc[jb][1] = sc[jb][2] = sc[jb][3] = 0.f;
        #pragma unroll
        for (int jp = 0; jp < 4; jp++) {
            #pragma unroll
            for (int kc = 0; kc < 4; kc++) {
                uint32_t kb[4];
                const uint32_t addr = sK + (uint32_t)(
                    ((2 * jp + (lq >> 1)) * 8 + lr) * KVSTR + kc * 16 + (lq & 1) * 8) * 2;
                ldsm_x4(kb, addr);
                mma_f16(sc[2 * jp],     qf[kc][0], qf[kc][1], qf[kc][2], qf[kc][3], kb[0], kb[1]);
                mma_f16(sc[2 * jp + 1], qf[kc][0], qf[kc][1], qf[kc][2], qf[kc][3], kb[2], kb[3]);
            }
        }

        // ---- causal mask (only if this tile can violate causality for this warp) ----
        if (j0 + 63 > m0 + qr) {
            #pragma unroll
            for (int jb = 0; jb < 8; jb++) {
                const int c0 = j0 + jb * 8 + 2 * tig;
                const int c1 = c0 + 1;
                if (c0 > tq0) sc[jb][0] = NEG_INF;
                if (c1 > tq0) sc[jb][1] = NEG_INF;
                if (c0 > tq1) sc[jb][2] = NEG_INF;
                if (c1 > tq1) sc[jb][3] = NEG_INF;
            }
        }
        float tm0 = NEG_INF, tm1 = NEG_INF;
        #pragma unroll
        for (int jb = 0; jb < 8; jb++) {
            tm0 = fmaxf(tm0, fmaxf(sc[jb][0], sc[jb][1]));
            tm1 = fmaxf(tm1, fmaxf(sc[jb][2], sc[jb][3]));
        }
        tm0 = fmaxf(tm0, __shfl_xor_sync(0xffffffffu, tm0, 1));
        tm0 = fmaxf(tm0, __shfl_xor_sync(0xffffffffu, tm0, 2));
        tm1 = fmaxf(tm1, __shfl_xor_sync(0xffffffffu, tm1, 1));
        tm1 = fmaxf(tm1, __shfl_xor_sync(0xffffffffu, tm1, 2));

        const float mn0 = fmaxf(mr0, tm0);
        const float mn1 = fmaxf(mr1, tm1);
        const float a0 = __expf(mr0 - mn0);
        const float a1 = __expf(mr1 - mn1);
        l0 *= a0; l1 *= a1;
        #pragma unroll
        for (int nb = 0; nb < 8; nb++) {
            oacc[nb][0] *= a0; oacc[nb][1] *= a0;
            oacc[nb][2] *= a1; oacc[nb][3] *= a1;
        }

        // ---- P = exp(S - m) -> A fragments ----
        uint32_t af[4][4];
        float ps0 = 0.f, ps1 = 0.f;
        #pragma unroll
        for (int kc = 0; kc < 4; kc++) {
            const int jA = 2 * kc, jB = 2 * kc + 1;
            const float pA0 = __expf(sc[jA][0] - mn0);
            const float pA1 = __expf(sc[jA][1] - mn0);
            const float pA2 = __expf(sc[jA][2] - mn1);
            const float pA3 = __expf(sc[jA][3] - mn1);
            const float pB0 = __expf(sc[jB][0] - mn0);
            const float pB1 = __expf(sc[jB][1] - mn0);
            const float pB2 = __expf(sc[jB][2] - mn1);
            const float pB3 = __expf(sc[jB][3] - mn1);
            ps0 += (pA0 + pA1) + (pB0 + pB1);
            ps1 += (pA2 + pA3) + (pB2 + pB3);
            af[kc][0] = pack_h2(pA0, pA1);
            af[kc][1] = pack_h2(pA2, pA3);
            af[kc][2] = pack_h2(pB0, pB1);
            af[kc][3] = pack_h2(pB2, pB3);
        }
        ps0 += __shfl_xor_sync(0xffffffffu, ps0, 1);
        ps0 += __shfl_xor_sync(0xffffffffu, ps0, 2);
        ps1 += __shfl_xor_sync(0xffffffffu, ps1, 1);
        ps1 += __shfl_xor_sync(0xffffffffu, ps1, 2);
        l0 += ps0; l1 += ps1;
        mr0 = mn0; mr1 = mn1;

        // ---- PV via ldmatrix.trans V fragments ----
        #pragma unroll
        for (int p = 0; p < 4; p++) {
            #pragma unroll
            for (int kc = 0; kc < 4; kc++) {
                uint32_t vb[4];
                const uint32_t addr = sV + (uint32_t)(
                    (kc * 16 + (lq & 1) * 8 + lr) * KVSTR + p * 16 + (lq >> 1) * 8) * 2;
                ldsm_x4_trans(vb, addr);
                mma_f16(oacc[2 * p],     af[kc][0], af[kc][1], af[kc][2], af[kc][3], vb[0], vb[1]);
                mma_f16(oacc[2 * p + 1], af[kc][0], af[kc][1], af[kc][2], af[kc][3], vb[2], vb[3]);
            }
        }
        __syncthreads();
    }

    // ---- epilogue: normalize, half out ----
    const float inv0 = 1.0f / l0;
    const float inv1 = 1.0f / l1;
    const size_t row0 = (size_t)(b * T_ + tq0);
    const size_t row1 = (size_t)(b * T_ + tq1);
    #pragma unroll
    for (int nb = 0; nb < 8; nb++) {
        const int col = h * D_ + nb * 8 + 2 * tig;
        *(__half2*)(out + row0 * E_ + col) =
            __floats2half2_rn(oacc[nb][0] * inv0, oacc[nb][1] * inv0);
        *(__half2*)(out + row1 * E_ + col) =
            __floats2half2_rn(oacc[nb][2] * inv1, oacc[nb][3] * inv1);
    }
}

// ---------------------------------------------------------------------------
// Launch
// ---------------------------------------------------------------------------
extern "C" void kernel_launch(void* const* d_in, const int* in_sizes, int n_in,
                              void* d_out, int out_size)
{
    const float* x      = (const float*)d_in[0];
    const float* ln1_g  = (const float*)d_in[1];
    const float* ln1_b  = (const float*)d_in[2];
    const float* ln2_g  = (const float*)d_in[3];
    const float* ln2_b  = (const float*)d_in[4];
    const float* W_qkv  = (const float*)d_in[5];
    const float* b_qkv  = (const float*)d_in[6];
    const float* W_o    = (const float*)d_in[7];
    const float* b_o    = (const float*)d_in[8];
    const float* W_fc   = (const float*)d_in[9];
    const float* b_fc   = (const float*)d_in[10];
    const float* W_proj = (const float*)d_in[11];
    const float* b_proj = (const float*)d_in[12];
    float* out = (float*)d_out;

    __half *p_lnH, *p_qkvH, *p_attnH, *p_fcH;
    float *p_x1;
    uint32_t *p_wqkvP, *p_woP, *p_wfcP, *p_wprojP;
    cudaGetSymbolAddress((void**)&p_lnH,    g_lnH);
    cudaGetSymbolAddress((void**)&p_qkvH,   g_qkvH);
    cudaGetSymbolAddress((void**)&p_attnH,  g_attnH);
    cudaGetSymbolAddress((void**)&p_x1,     g_x1);
    cudaGetSymbolAddress((void**)&p_fcH,    g_fcH);
    cudaGetSymbolAddress((void**)&p_wqkvP,  g_wqkvP);
    cudaGetSymbolAddress((void**)&p_woP,    g_woP);
    cudaGetSymbolAddress((void**)&p_wfcP,   g_wfcP);
    cudaGetSymbolAddress((void**)&p_wprojP, g_wprojP);

    cudaFuncSetAttribute(gemm_h_kernel<0>, cudaFuncAttributeMaxDynamicSharedMemorySize, GEMM_H_SMEM);
    cudaFuncSetAttribute(gemm_h_kernel<1>, cudaFuncAttributeMaxDynamicSharedMemorySize, GEMM_H_SMEM);
    cudaFuncSetAttribute(gemm_h_kernel<2>, cudaFuncAttributeMaxDynamicSharedMemorySize, GEMM_H_SMEM);
    cudaFuncSetAttribute(gemm_h_kernel<3>, cudaFuncAttributeMaxDynamicSharedMemorySize, GEMM_H_SMEM);
    cudaFuncSetAttribute(attn_h_kernel,    cudaFuncAttributeMaxDynamicSharedMemorySize, ATT_SMEM);

    // 0. all weight packs in one launch
    pack_all_kernel<<<3072, 256>>>(W_qkv, p_wqkvP, W_o, p_woP, W_fc, p_wfcP, W_proj, p_wprojP);

    // 1. ln1 = LN(x) -> half
    layernorm_kernel<<<M_ / 8, 256>>>(x, ln1_g, ln1_b, p_lnH);
    // 2. qkv = ln1 @ W_qkv + b_qkv -> half
    gemm_h_kernel<3><<<dim3(QKV_N / 128, M_ / 128), 128, GEMM_H_SMEM>>>(
        p_lnH, p_wqkvP, b_qkv, nullptr, p_qkvH, QKV_N, E_);
    // 3. attention (128-query blocks)
    attn_h_kernel<<<dim3(T_ / 128, B_ * H_), 256, ATT_SMEM>>>(p_qkvH, p_attnH);
    // 4. x1 = x + attn @ W_o + b_o (fp32 out)
    gemm_h_kernel<1><<<dim3(E_ / 128, M_ / 128), 128, GEMM_H_SMEM>>>(
        p_attnH, p_woP, b_o, x, p_x1, E_, E_);
    // 5. ln2 = LN(x1) -> half
    layernorm_kernel<<<M_ / 8, 256>>>(p_x1, ln2_g, ln2_b, p_lnH);
    // 6. fc = gelu(ln2 @ W_fc + b_fc) -> half
    gemm_h_kernel<2><<<dim3(FC_N / 128, M_ / 128), 128, GEMM_H_SMEM>>>(
        p_lnH, p_wfcP, b_fc, nullptr, p_fcH, FC_N, E_);
    // 7. out = x1 + fc @ W_proj + b_proj (fp32 out)
    gemm_h_kernel<1><<<dim3(E_ / 128, M_ / 128), 128, GEMM_H_SMEM>>>(
        p_fcH, p_wprojP, b_proj, p_x1, out, E_, FC_N);
}

// round 16
// speedup vs baseline: 1.0192x; 1.0192x over previous
#include <cuda_runtime.h>
#include <cuda_fp16.h>
#include <math.h>
#include <stdint.h>

// ---------------------------------------------------------------------------
// Problem constants
// ---------------------------------------------------------------------------
#define B_  2
#define T_  2048
#define E_  1024
#define H_  16
#define D_  64
#define M_  (B_ * T_)          // 4096
#define QKV_N (3 * E_)         // 3072
#define FC_N  (4 * E_)         // 4096

// ---------------------------------------------------------------------------
// Scratch (device globals; allocations forbidden)
// ---------------------------------------------------------------------------
__device__ __half g_lnH  [(size_t)M_ * E_];
__device__ __half g_qkvH [(size_t)M_ * QKV_N];
__device__ __half g_attnH[(size_t)M_ * E_];
__device__ float  g_x1   [(size_t)M_ * E_];
__device__ __half g_fcH  [(size_t)M_ * FC_N];
__device__ uint32_t g_wqkvP [(size_t)QKV_N * E_ / 2];
__device__ uint32_t g_woP   [(size_t)E_ * E_ / 2];
__device__ uint32_t g_wfcP  [(size_t)FC_N * E_ / 2];
__device__ uint32_t g_wprojP[(size_t)E_ * FC_N / 2];

// ---------------------------------------------------------------------------
// Helpers
// ---------------------------------------------------------------------------
__device__ __forceinline__ uint32_t smem_u32(const void* p) {
    uint32_t a;
    asm("{ .reg .u64 t; cvta.to.shared.u64 t, %1; cvt.u32.u64 %0, t; }" : "=r"(a) : "l"(p));
    return a;
}
#define CP_ASYNC16(dst, src) \
    asm volatile("cp.async.cg.shared.global [%0], [%1], 16;" :: "r"(dst), "l"(src) : "memory")
#define CP_COMMIT() asm volatile("cp.async.commit_group;" ::: "memory")

__device__ __forceinline__ void ldsm_x4(uint32_t (&r)[4], uint32_t addr) {
    asm volatile("ldmatrix.sync.aligned.m8n8.x4.shared.b16 {%0,%1,%2,%3}, [%4];"
                 : "=r"(r[0]), "=r"(r[1]), "=r"(r[2]), "=r"(r[3]) : "r"(addr));
}
__device__ __forceinline__ void ldsm_x4_trans(uint32_t (&r)[4], uint32_t addr) {
    asm volatile("ldmatrix.sync.aligned.m8n8.x4.trans.shared.b16 {%0,%1,%2,%3}, [%4];"
                 : "=r"(r[0]), "=r"(r[1]), "=r"(r[2]), "=r"(r[3]) : "r"(addr));
}

// fp16 MMA: m16n8k16, fp32 accumulate
__device__ __forceinline__ void mma_f16(float (&c)[4],
                                        uint32_t a0, uint32_t a1, uint32_t a2, uint32_t a3,
                                        uint32_t b0, uint32_t b1) {
    asm volatile(
        "mma.sync.aligned.m16n8k16.row.col.f32.f16.f16.f32 "
        "{%0,%1,%2,%3}, {%4,%5,%6,%7}, {%8,%9}, {%0,%1,%2,%3};"
        : "+f"(c[0]), "+f"(c[1]), "+f"(c[2]), "+f"(c[3])
        : "r"(a0), "r"(a1), "r"(a2), "r"(a3), "r"(b0), "r"(b1));
}
__device__ __forceinline__ uint32_t pack_h2(float lo, float hi) {
    const __half2 h = __floats2half2_rn(lo, hi);
    return *(const uint32_t*)&h;
}

// ---------------------------------------------------------------------------
// Merged weight pack, with block-id offset so it can be split across streams.
// Effective id e = bid + base:
//   [0,768) qkv | [768,1024) W_o | [1024,2048) W_fc | [2048,3072) W_proj
// ---------------------------------------------------------------------------
__global__ void pack_all_kernel(const float* __restrict__ W0, uint32_t* __restrict__ P0,
                                const float* __restrict__ W1, uint32_t* __restrict__ P1,
                                const float* __restrict__ W2, uint32_t* __restrict__ P2,
                                const float* __restrict__ W3, uint32_t* __restrict__ P3,
                                int base)
{
    __shared__ float ws[32][132];
    const int bid = blockIdx.x + base;
    const int tid = threadIdx.x;               // 256

    const float* W; uint32_t* Wp; int N, ntx, nkt, r;
    if (bid < 768)       { W = W0; Wp = P0; N = QKV_N; ntx = 24; nkt = 32;  r = bid; }
    else if (bid < 1024) { W = W1; Wp = P1; N = E_;    ntx = 8;  nkt = 32;  r = bid - 768; }
    else if (bid < 2048) { W = W2; Wp = P2; N = FC_N;  ntx = 32; nkt = 32;  r = bid - 1024; }
    else                 { W = W3; Wp = P3; N = E_;    ntx = 8;  nkt = 128; r = bid - 2048; }
    const int nt = r % ntx;
    const int kt = r / ntx;

    const float* src = W + (size_t)(kt * 32) * N + nt * 128;
    #pragma unroll
    for (int i = 0; i < 4; i++) {
        const int idx = tid + i * 256;
        const int rr = idx >> 5, c4 = idx & 31;
        *(float4*)&ws[rr][c4 * 4] = *(const float4*)(src + (size_t)rr * N + c4 * 4);
    }
    __syncthreads();

    uint32_t* dst = Wp + ((size_t)nt * nkt + kt) * 2048;
    #pragma unroll
    for (int i = 0; i < 8; i++) {
        const int o = tid + i * 256;
        const int s = o >> 6;
        const int lane = (o >> 1) & 31;
        const int reg = o & 1;
        const int kbb = s >> 4, nb = s & 15;
        const int g = lane >> 2, tig = lane & 3;
        const int k = kbb * 16 + reg * 8 + 2 * tig;
        const int n = nb * 8 + g;
        dst[o] = pack_h2(ws[k][n], ws[k + 1][n]);
    }
}

// ---------------------------------------------------------------------------
// fp16 mma.sync GEMM: BM=BN=128, BK=64 per stage, 3-stage cp.async pipeline.
// (Round-14 champion config — unchanged.)
// EPI: 0=bias (fp32 C), 1=bias+res (fp32 C), 2=bias+GELU (half C), 3=bias (half C)
// ---------------------------------------------------------------------------
#define SA_STR_H   72
#define SA_H_BYTES (128 * SA_STR_H * 2)      // 18432
#define SB_H_BYTES 16384
#define BUF_H      (SA_H_BYTES + SB_H_BYTES) // 34816
#define GEMM_H_SMEM (3 * BUF_H)              // 104448

template<int EPI>
__global__ void __launch_bounds__(128, 2)
gemm_h_kernel(const __half* __restrict__ A, const uint32_t* __restrict__ Wp,
              const float* __restrict__ bias, const float* __restrict__ res,
              void* __restrict__ Cv, int N, int K)
{
    extern __shared__ char smem[];
    const uint32_t sbase = smem_u32(smem);
    float* Cf = (float*)Cv;
    __half* Ch = (__half*)Cv;

    const int tid  = threadIdx.x;
    const int wid  = tid >> 5;
    const int lane = tid & 31;
    const int g    = lane >> 2;
    const int tig  = lane & 3;
    const int wm   = (wid >> 1) * 64;
    const int wn   = (wid & 1) * 64;
    const int m0   = blockIdx.y * 128;
    const int n0   = blockIdx.x * 128;

    const int ntile = K >> 6;
    const size_t wtile0 = (size_t)blockIdx.x * (K >> 5) * 2048;

    const int am = tid >> 3;
    const int ac = tid & 7;

    const int arow = lane & 15;
    const int acol = (lane >> 4) * 8;

    float acc[4][8][4];
    #pragma unroll
    for (int mt = 0; mt < 4; mt++)
        #pragma unroll
        for (int nb = 0; nb < 8; nb++)
            #pragma unroll
            for (int r = 0; r < 4; r++) acc[mt][nb][r] = 0.f;

    auto load_tile = [&](int buf, int kt) {
        const uint32_t sA = sbase + buf * BUF_H;
        const uint32_t sB = sA + SA_H_BYTES;
        const __half* asrc = A + (size_t)(m0 + am) * K + kt * 64 + ac * 8;
        #pragma unroll
        for (int i = 0; i < 8; i++) {
            CP_ASYNC16(sA + (uint32_t)(am + i * 16) * (SA_STR_H * 2) + ac * 16,
                       asrc + (size_t)i * 16 * K);
        }
        const uint32_t* bsrc = Wp + wtile0 + (size_t)kt * 4096 + tid * 4;
        #pragma unroll
        for (int i = 0; i < 8; i++) {
            CP_ASYNC16(sB + (uint32_t)(tid + i * 128) * 16, bsrc + i * 512);
        }
        CP_COMMIT();
    };

    load_tile(0, 0);
    if (ntile > 1) load_tile(1, 1);

    for (int t = 0; t < ntile; t++) {
        if (t + 1 < ntile) {
            asm volatile("cp.async.wait_group 1;" ::: "memory");
        } else {
            asm volatile("cp.async.wait_group 0;" ::: "memory");
        }
        __syncthreads();
        if (t + 2 < ntile) load_tile((t + 2) % 3, t + 2);

        const int cur = t % 3;
        const uint32_t sA = sbase + cur * BUF_H;
        const uint32_t* Bs = (const uint32_t*)(smem + cur * BUF_H + SA_H_BYTES);

        #pragma unroll
        for (int kbb = 0; kbb < 4; kbb++) {
            uint32_t a[4][4];
            #pragma unroll
            for (int mt = 0; mt < 4; mt++) {
                const uint32_t addr = sA +
                    (uint32_t)((wm + mt * 16 + arow) * SA_STR_H + kbb * 16 + acol) * 2;
                ldsm_x4(a[mt], addr);
            }
            const uint32_t* Bsub = Bs + (kbb >> 1) * 2048;
            #pragma unroll
            for (int nb = 0; nb < 8; nb++) {
                const int s = (kbb & 1) * 16 + (wn >> 3) + nb;
                const uint2 bb = *(const uint2*)(Bsub + s * 64 + lane * 2);
                #pragma unroll
                for (int mt = 0; mt < 4; mt++)
                    mma_f16(acc[mt][nb], a[mt][0], a[mt][1], a[mt][2], a[mt][3],
                            bb.x, bb.y);
            }
        }
    }

    #pragma unroll
    for (int mt = 0; mt < 4; mt++) {
        const size_t r0 = (size_t)(m0 + wm + mt * 16 + g);
        #pragma unroll
        for (int nb = 0; nb < 8; nb++) {
            const int col = n0 + wn + nb * 8 + 2 * tig;
            const float2 bv = *(const float2*)(bias + col);
            #pragma unroll
            for (int hh = 0; hh < 2; hh++) {
                const size_t row = r0 + hh * 8;
                float vx = acc[mt][nb][hh * 2 + 0] + bv.x;
                float vy = acc[mt][nb][hh * 2 + 1] + bv.y;
                if (EPI == 1) {
                    const float2 r2 = *(const float2*)(res + row * N + col);
                    vx += r2.x; vy += r2.y;
                }
                if (EPI == 2) {
                    vx = 0.5f * vx * (1.0f + erff(vx * 0.70710678118654752f));
                    vy = 0.5f * vy * (1.0f + erff(vy * 0.70710678118654752f));
                }
                if (EPI == 2 || EPI == 3) {
                    *(__half2*)(Ch + row * N + col) = __floats2half2_rn(vx, vy);
                } else {
                    float2 o2; o2.x = vx; o2.y = vy;
                    *(float2*)(Cf + row * N + col) = o2;
                }
            }
        }
    }
}

// ---------------------------------------------------------------------------
// LayerNorm: warp-per-row (unchanged)
// ---------------------------------------------------------------------------
__global__ void layernorm_kernel(const float* __restrict__ x,
                                 const float* __restrict__ gamma,
                                 const float* __restrict__ beta,
                                 __half* __restrict__ out)
{
    const int wid  = threadIdx.x >> 5;
    const int lane = threadIdx.x & 31;
    const int row  = blockIdx.x * 8 + wid;

    const float4* xr = (const float4*)(x + (size_t)row * E_);
    float4 v[8];
    float s = 0.f, ss = 0.f;
    #pragma unroll
    for (int i = 0; i < 8; i++) {
        v[i] = xr[lane + 32 * i];
        s  += (v[i].x + v[i].y) + (v[i].z + v[i].w);
        ss += (v[i].x * v[i].x + v[i].y * v[i].y) + (v[i].z * v[i].z + v[i].w * v[i].w);
    }
    #pragma unroll
    for (int o = 16; o > 0; o >>= 1) {
        s  += __shfl_xor_sync(0xffffffffu, s,  o);
        ss += __shfl_xor_sync(0xffffffffu, ss, o);
    }
    const float mean = s * (1.0f / E_);
    const float var  = ss * (1.0f / E_) - mean * mean;
    const float r    = rsqrtf(var + 1e-5f);

    const float4* gp = (const float4*)gamma;
    const float4* bp = (const float4*)beta;
    __half2* op = (__half2*)(out + (size_t)row * E_);
    #pragma unroll
    for (int i = 0; i < 8; i++) {
        const int c4 = lane + 32 * i;
        const float4 gv = gp[c4];
        const float4 bv = bp[c4];
        op[c4 * 2 + 0] = __floats2half2_rn((v[i].x - mean) * r * gv.x + bv.x,
                                           (v[i].y - mean) * r * gv.y + bv.y);
        op[c4 * 2 + 1] = __floats2half2_rn((v[i].z - mean) * r * gv.z + bv.z,
                                           (v[i].w - mean) * r * gv.w + bv.w);
    }
}

// ---------------------------------------------------------------------------
// Flash attention: Round-14 champion config (64-query blocks, 128 threads,
// ldmatrix + double-buffered K/V, diagonal-only mask, longest-first order).
// ---------------------------------------------------------------------------
#define KVSTR 72
#define KVT   (64 * KVSTR)
#define ATT_SMEM (5 * KVT * 2)             // 46080 bytes

__global__ void __launch_bounds__(128, 3)
attn_h_kernel(const __half* __restrict__ qkv, __half* __restrict__ out)
{
    extern __shared__ __half smh[];
    const uint32_t sQ = smem_u32(smh);

    const int bh  = blockIdx.y;
    const int b   = bh >> 4;
    const int h   = bh & 15;
    const int m0  = (gridDim.x - 1 - blockIdx.x) * 64;
    const int tid = threadIdx.x;
    const int wid = tid >> 5;
    const int lane = tid & 31;
    const int g    = lane >> 2;
    const int tig  = lane & 3;
    const int qr   = wid * 16;
    const int lq   = lane >> 3;
    const int lr   = lane & 7;
    const float NEG_INF = __int_as_float(0xff800000);

    const size_t baseQ = ((size_t)(b * T_ + m0)) * QKV_N + h * D_;
    #pragma unroll
    for (int i = 0; i < 4; i++) {
        const int idx = tid + i * 128;
        const int r = idx >> 3, c = idx & 7;
        CP_ASYNC16(sQ + (uint32_t)(r * KVSTR + c * 8) * 2,
                   qkv + baseQ + (size_t)r * QKV_N + c * 8);
    }
    CP_COMMIT();

    auto load_kv = [&](int stage, int t) {
        const uint32_t sK = sQ + (uint32_t)(1 + 2 * stage) * (KVT * 2);
        const uint32_t sV = sK + KVT * 2;
        const size_t baseK = ((size_t)(b * T_ + t * 64)) * QKV_N + E_ + h * D_;
        #pragma unroll
        for (int i = 0; i < 4; i++) {
            const int idx = tid + i * 128;
            const int r = idx >> 3, c = idx & 7;
            const __half* src = qkv + baseK + (size_t)r * QKV_N + c * 8;
            CP_ASYNC16(sK + (uint32_t)(r * KVSTR + c * 8) * 2, src);
            CP_ASYNC16(sV + (uint32_t)(r * KVSTR + c * 8) * 2, src + E_);
        }
        CP_COMMIT();
    };
    load_kv(0, 0);

    asm volatile("cp.async.wait_group 0;" ::: "memory");
    __syncthreads();

    const __half2 qscale = __half2half2(__float2half_rn(0.125f));
    uint32_t qf[4][4];
    #pragma unroll
    for (int kc = 0; kc < 4; kc++) {
        const __half* Qp = smh;
        #pragma unroll
        for (int j = 0; j < 4; j++) {
            const int rr = qr + g + (j & 1) * 8;
            const int cc = kc * 16 + 2 * tig + (j >> 1) * 8;
            __half2 q2 = *(const __half2*)(Qp + rr * KVSTR + cc);
            q2 = __hmul2(q2, qscale);
            qf[kc][j] = *(const uint32_t*)&q2;
        }
    }

    float oacc[8][4];
    #pragma unroll
    for (int nb = 0; nb < 8; nb++)
        #pragma unroll
        for (int r = 0; r < 4; r++) oacc[nb][r] = 0.f;
    float mr0 = NEG_INF, mr1 = NEG_INF, l0 = 0.f, l1 = 0.f;

    const int tq0 = m0 + qr + g;
    const int tq1 = tq0 + 8;
    const int ntile = (m0 >> 6) + 1;

    for (int t = 0; t < ntile; t++) {
        const int j0 = t * 64;
        const int cur = t & 1;
        if (t + 1 < ntile) {
            load_kv(cur ^ 1, t + 1);
            asm volatile("cp.async.wait_group 1;" ::: "memory");
        } else {
            asm volatile("cp.async.wait_group 0;" ::: "memory");
        }
        __syncthreads();

        const uint32_t sK = sQ + (uint32_t)(1 + 2 * cur) * (KVT * 2);
        const uint32_t sV = sK + KVT * 2;

        float sc[8][4];
        #pragma unroll
        for (int jb = 0; jb < 8; jb++)
            sc[jb][0] = sc[jb][1] = sc[jb][2] = sc[jb][3] = 0.f;
        #pragma unroll
        for (int jp = 0; jp < 4; jp++) {
            #pragma unroll
            for (int kc = 0; kc < 4; kc++) {
                uint32_t kb[4];
                const uint32_t addr = sK + (uint32_t)(
                    ((2 * jp + (lq >> 1)) * 8 + lr) * KVSTR + kc * 16 + (lq & 1) * 8) * 2;
                ldsm_x4(kb, addr);
                mma_f16(sc[2 * jp],     qf[kc][0], qf[kc][1], qf[kc][2], qf[kc][3], kb[0], kb[1]);
                mma_f16(sc[2 * jp + 1], qf[kc][0], qf[kc][1], qf[kc][2], qf[kc][3], kb[2], kb[3]);
            }
        }

        if (t == ntile - 1) {
            #pragma unroll
            for (int jb = 0; jb < 8; jb++) {
                const int c0 = j0 + jb * 8 + 2 * tig;
                const int c1 = c0 + 1;
                if (c0 > tq0) sc[jb][0] = NEG_INF;
                if (c1 > tq0) sc[jb][1] = NEG_INF;
                if (c0 > tq1) sc[jb][2] = NEG_INF;
                if (c1 > tq1) sc[jb][3] = NEG_INF;
            }
        }
        float tm0 = NEG_INF, tm1 = NEG_INF;
        #pragma unroll
        for (int jb = 0; jb < 8; jb++) {
            tm0 = fmaxf(tm0, fmaxf(sc[jb][0], sc[jb][1]));
            tm1 = fmaxf(tm1, fmaxf(sc[jb][2], sc[jb][3]));
        }
        tm0 = fmaxf(tm0, __shfl_xor_sync(0xffffffffu, tm0, 1));
        tm0 = fmaxf(tm0, __shfl_xor_sync(0xffffffffu, tm0, 2));
        tm1 = fmaxf(tm1, __shfl_xor_sync(0xffffffffu, tm1, 1));
        tm1 = fmaxf(tm1, __shfl_xor_sync(0xffffffffu, tm1, 2));

        const float mn0 = fmaxf(mr0, tm0);
        const float mn1 = fmaxf(mr1, tm1);
        const float a0 = __expf(mr0 - mn0);
        const float a1 = __expf(mr1 - mn1);
        l0 *= a0; l1 *= a1;
        #pragma unroll
        for (int nb = 0; nb < 8; nb++) {
            oacc[nb][0] *= a0; oacc[nb][1] *= a0;
            oacc[nb][2] *= a1; oacc[nb][3] *= a1;
        }

        uint32_t af[4][4];
        float ps0 = 0.f, ps1 = 0.f;
        #pragma unroll
        for (int kc = 0; kc < 4; kc++) {
            const int jA = 2 * kc, jB = 2 * kc + 1;
            const float pA0 = __expf(sc[jA][0] - mn0);
            const float pA1 = __expf(sc[jA][1] - mn0);
            const float pA2 = __expf(sc[jA][2] - mn1);
            const float pA3 = __expf(sc[jA][3] - mn1);
            const float pB0 = __expf(sc[jB][0] - mn0);
            const float pB1 = __expf(sc[jB][1] - mn0);
            const float pB2 = __expf(sc[jB][2] - mn1);
            const float pB3 = __expf(sc[jB][3] - mn1);
            ps0 += (pA0 + pA1) + (pB0 + pB1);
            ps1 += (pA2 + pA3) + (pB2 + pB3);
            af[kc][0] = pack_h2(pA0, pA1);
            af[kc][1] = pack_h2(pA2, pA3);
            af[kc][2] = pack_h2(pB0, pB1);
            af[kc][3] = pack_h2(pB2, pB3);
        }
        ps0 += __shfl_xor_sync(0xffffffffu, ps0, 1);
        ps0 += __shfl_xor_sync(0xffffffffu, ps0, 2);
        ps1 += __shfl_xor_sync(0xffffffffu, ps1, 1);
        ps1 += __shfl_xor_sync(0xffffffffu, ps1, 2);
        l0 += ps0; l1 += ps1;
        mr0 = mn0; mr1 = mn1;

        #pragma unroll
        for (int p = 0; p < 4; p++) {
            #pragma unroll
            for (int kc = 0; kc < 4; kc++) {
                uint32_t vb[4];
                const uint32_t addr = sV + (uint32_t)(
                    (kc * 16 + (lq & 1) * 8 + lr) * KVSTR + p * 16 + (lq >> 1) * 8) * 2;
                ldsm_x4_trans(vb, addr);
                mma_f16(oacc[2 * p],     af[kc][0], af[kc][1], af[kc][2], af[kc][3], vb[0], vb[1]);
                mma_f16(oacc[2 * p + 1], af[kc][0], af[kc][1], af[kc][2], af[kc][3], vb[2], vb[3]);
            }
        }
        __syncthreads();
    }

    const float inv0 = 1.0f / l0;
    const float inv1 = 1.0f / l1;
    const size_t row0 = (size_t)(b * T_ + tq0);
    const size_t row1 = (size_t)(b * T_ + tq1);
    #pragma unroll
    for (int nb = 0; nb < 8; nb++) {
        const int col = h * D_ + nb * 8 + 2 * tig;
        *(__half2*)(out + row0 * E_ + col) =
            __floats2half2_rn(oacc[nb][0] * inv0, oacc[nb][1] * inv0);
        *(__half2*)(out + row1 * E_ + col) =
            __floats2half2_rn(oacc[nb][2] * inv1, oacc[nb][3] * inv1);
    }
}

// ---------------------------------------------------------------------------
// Launch — second stream hides the non-qkv weight packs behind LN1/qkv/attn.
// Stream/event creation is host-side only (no device allocations) and the
// fork/join via events is CUDA-graph-capturable.
// ---------------------------------------------------------------------------
extern "C" void kernel_launch(void* const* d_in, const int* in_sizes, int n_in,
                              void* d_out, int out_size)
{
    const float* x      = (const float*)d_in[0];
    const float* ln1_g  = (const float*)d_in[1];
    const float* ln1_b  = (const float*)d_in[2];
    const float* ln2_g  = (const float*)d_in[3];
    const float* ln2_b  = (const float*)d_in[4];
    const float* W_qkv  = (const float*)d_in[5];
    const float* b_qkv  = (const float*)d_in[6];
    const float* W_o    = (const float*)d_in[7];
    const float* b_o    = (const float*)d_in[8];
    const float* W_fc   = (const float*)d_in[9];
    const float* b_fc   = (const float*)d_in[10];
    const float* W_proj = (const float*)d_in[11];
    const float* b_proj = (const float*)d_in[12];
    float* out = (float*)d_out;

    __half *p_lnH, *p_qkvH, *p_attnH, *p_fcH;
    float *p_x1;
    uint32_t *p_wqkvP, *p_woP, *p_wfcP, *p_wprojP;
    cudaGetSymbolAddress((void**)&p_lnH,    g_lnH);
    cudaGetSymbolAddress((void**)&p_qkvH,   g_qkvH);
    cudaGetSymbolAddress((void**)&p_attnH,  g_attnH);
    cudaGetSymbolAddress((void**)&p_x1,     g_x1);
    cudaGetSymbolAddress((void**)&p_fcH,    g_fcH);
    cudaGetSymbolAddress((void**)&p_wqkvP,  g_wqkvP);
    cudaGetSymbolAddress((void**)&p_woP,    g_woP);
    cudaGetSymbolAddress((void**)&p_wfcP,   g_wfcP);
    cudaGetSymbolAddress((void**)&p_wprojP, g_wprojP);

    cudaFuncSetAttribute(gemm_h_kernel<0>, cudaFuncAttributeMaxDynamicSharedMemorySize, GEMM_H_SMEM);
    cudaFuncSetAttribute(gemm_h_kernel<1>, cudaFuncAttributeMaxDynamicSharedMemorySize, GEMM_H_SMEM);
    cudaFuncSetAttribute(gemm_h_kernel<2>, cudaFuncAttributeMaxDynamicSharedMemorySize, GEMM_H_SMEM);
    cudaFuncSetAttribute(gemm_h_kernel<3>, cudaFuncAttributeMaxDynamicSharedMemorySize, GEMM_H_SMEM);
    cudaFuncSetAttribute(attn_h_kernel,    cudaFuncAttributeMaxDynamicSharedMemorySize, ATT_SMEM);

    // side stream for the W_o/W_fc/W_proj packs (kernel_launch is only called
    // a handful of times — correctness + capture — so these tiny host objects
    // are created at most a few times; no device memory is involved)
    cudaStream_t s2;
    cudaStreamCreateWithFlags(&s2, cudaStreamNonBlocking);
    cudaEvent_t evFork, evJoin;
    cudaEventCreateWithFlags(&evFork, cudaEventDisableTiming);
    cudaEventCreateWithFlags(&evJoin, cudaEventDisableTiming);

    // 0a. qkv pack (critical path) on main stream
    pack_all_kernel<<<768, 256>>>(W_qkv, p_wqkvP, W_o, p_woP, W_fc, p_wfcP, W_proj, p_wprojP, 0);

    // fork: remaining packs on s2, overlapping LN1 + qkv GEMM + attention
    cudaEventRecord(evFork, 0);
    cudaStreamWaitEvent(s2, evFork, 0);
    pack_all_kernel<<<2304, 256, 0, s2>>>(W_qkv, p_wqkvP, W_o, p_woP, W_fc, p_wfcP, W_proj, p_wprojP, 768);
    cudaEventRecord(evJoin, s2);

    // 1. ln1 = LN(x) -> half
    layernorm_kernel<<<M_ / 8, 256>>>(x, ln1_g, ln1_b, p_lnH);
    // 2. qkv = ln1 @ W_qkv + b_qkv -> half
    gemm_h_kernel<3><<<dim3(QKV_N / 128, M_ / 128), 128, GEMM_H_SMEM>>>(
        p_lnH, p_wqkvP, b_qkv, nullptr, p_qkvH, QKV_N, E_);
    // 3. attention
    attn_h_kernel<<<dim3(T_ / 64, B_ * H_), 128, ATT_SMEM>>>(p_qkvH, p_attnH);

    // join: W_o/W_fc/W_proj packs must be done before step 4
    cudaStreamWaitEvent(0, evJoin, 0);

    // 4. x1 = x + attn @ W_o + b_o (fp32 out)
    gemm_h_kernel<1><<<dim3(E_ / 128, M_ / 128), 128, GEMM_H_SMEM>>>(
        p_attnH, p_woP, b_o, x, p_x1, E_, E_);
    // 5. ln2 = LN(x1) -> half
    layernorm_kernel<<<M_ / 8, 256>>>(p_x1, ln2_g, ln2_b, p_lnH);
    // 6. fc = gelu(ln2 @ W_fc + b_fc) -> half
    gemm_h_kernel<2><<<dim3(FC_N / 128, M_ / 128), 128, GEMM_H_SMEM>>>(
        p_lnH, p_wfcP, b_fc, nullptr, p_fcH, FC_N, E_);
    // 7. out = x1 + fc @ W_proj + b_proj (fp32 out)
    gemm_h_kernel<1><<<dim3(E_ / 128, M_ / 128), 128, GEMM_H_SMEM>>>(
        p_fcH, p_wprojP, b_proj, p_x1, out, E_, FC_N);
}

// round 17
// speedup vs baseline: 1.0251x; 1.0058x over previous
#include <cuda_runtime.h>
#include <cuda_fp16.h>
#include <math.h>
#include <stdint.h>

// ---------------------------------------------------------------------------
// Problem constants
// ---------------------------------------------------------------------------
#define B_  2
#define T_  2048
#define E_  1024
#define H_  16
#define D_  64
#define M_  (B_ * T_)          // 4096
#define QKV_N (3 * E_)         // 3072
#define FC_N  (4 * E_)         // 4096

// ---------------------------------------------------------------------------
// Scratch (device globals; allocations forbidden)
// ---------------------------------------------------------------------------
__device__ __half g_lnH  [(size_t)M_ * E_];
__device__ __half g_qkvH [(size_t)M_ * QKV_N];
__device__ __half g_attnH[(size_t)M_ * E_];
__device__ float  g_x1   [(size_t)M_ * E_];
__device__ __half g_fcH  [(size_t)M_ * FC_N];
__device__ uint32_t g_wqkvP [(size_t)QKV_N * E_ / 2];
__device__ uint32_t g_woP   [(size_t)E_ * E_ / 2];
__device__ uint32_t g_wfcP  [(size_t)FC_N * E_ / 2];
__device__ uint32_t g_wprojP[(size_t)E_ * FC_N / 2];

// ---------------------------------------------------------------------------
// Helpers
// ---------------------------------------------------------------------------
__device__ __forceinline__ uint32_t smem_u32(const void* p) {
    uint32_t a;
    asm("{ .reg .u64 t; cvta.to.shared.u64 t, %1; cvt.u32.u64 %0, t; }" : "=r"(a) : "l"(p));
    return a;
}
#define CP_ASYNC16(dst, src) \
    asm volatile("cp.async.cg.shared.global [%0], [%1], 16;" :: "r"(dst), "l"(src) : "memory")
#define CP_COMMIT() asm volatile("cp.async.commit_group;" ::: "memory")

__device__ __forceinline__ void ldsm_x4(uint32_t (&r)[4], uint32_t addr) {
    asm volatile("ldmatrix.sync.aligned.m8n8.x4.shared.b16 {%0,%1,%2,%3}, [%4];"
                 : "=r"(r[0]), "=r"(r[1]), "=r"(r[2]), "=r"(r[3]) : "r"(addr));
}
__device__ __forceinline__ void ldsm_x4_trans(uint32_t (&r)[4], uint32_t addr) {
    asm volatile("ldmatrix.sync.aligned.m8n8.x4.trans.shared.b16 {%0,%1,%2,%3}, [%4];"
                 : "=r"(r[0]), "=r"(r[1]), "=r"(r[2]), "=r"(r[3]) : "r"(addr));
}

// fp16 MMA: m16n8k16, fp32 accumulate
__device__ __forceinline__ void mma_f16(float (&c)[4],
                                        uint32_t a0, uint32_t a1, uint32_t a2, uint32_t a3,
                                        uint32_t b0, uint32_t b1) {
    asm volatile(
        "mma.sync.aligned.m16n8k16.row.col.f32.f16.f16.f32 "
        "{%0,%1,%2,%3}, {%4,%5,%6,%7}, {%8,%9}, {%0,%1,%2,%3};"
        : "+f"(c[0]), "+f"(c[1]), "+f"(c[2]), "+f"(c[3])
        : "r"(a0), "r"(a1), "r"(a2), "r"(a3), "r"(b0), "r"(b1));
}
__device__ __forceinline__ uint32_t pack_h2(float lo, float hi) {
    const __half2 h = __floats2half2_rn(lo, hi);
    return *(const uint32_t*)&h;
}

// ---------------------------------------------------------------------------
// Merged weight pack, split across streams via block-id offset (unchanged)
// ---------------------------------------------------------------------------
__global__ void pack_all_kernel(const float* __restrict__ W0, uint32_t* __restrict__ P0,
                                const float* __restrict__ W1, uint32_t* __restrict__ P1,
                                const float* __restrict__ W2, uint32_t* __restrict__ P2,
                                const float* __restrict__ W3, uint32_t* __restrict__ P3,
                                int base)
{
    __shared__ float ws[32][132];
    const int bid = blockIdx.x + base;
    const int tid = threadIdx.x;               // 256

    const float* W; uint32_t* Wp; int N, ntx, nkt, r;
    if (bid < 768)       { W = W0; Wp = P0; N = QKV_N; ntx = 24; nkt = 32;  r = bid; }
    else if (bid < 1024) { W = W1; Wp = P1; N = E_;    ntx = 8;  nkt = 32;  r = bid - 768; }
    else if (bid < 2048) { W = W2; Wp = P2; N = FC_N;  ntx = 32; nkt = 32;  r = bid - 1024; }
    else                 { W = W3; Wp = P3; N = E_;    ntx = 8;  nkt = 128; r = bid - 2048; }
    const int nt = r % ntx;
    const int kt = r / ntx;

    const float* src = W + (size_t)(kt * 32) * N + nt * 128;
    #pragma unroll
    for (int i = 0; i < 4; i++) {
        const int idx = tid + i * 256;
        const int rr = idx >> 5, c4 = idx & 31;
        *(float4*)&ws[rr][c4 * 4] = *(const float4*)(src + (size_t)rr * N + c4 * 4);
    }
    __syncthreads();

    uint32_t* dst = Wp + ((size_t)nt * nkt + kt) * 2048;
    #pragma unroll
    for (int i = 0; i < 8; i++) {
        const int o = tid + i * 256;
        const int s = o >> 6;
        const int lane = (o >> 1) & 31;
        const int reg = o & 1;
        const int kbb = s >> 4, nb = s & 15;
        const int g = lane >> 2, tig = lane & 3;
        const int k = kbb * 16 + reg * 8 + 2 * tig;
        const int n = nb * 8 + g;
        dst[o] = pack_h2(ws[k][n], ws[k + 1][n]);
    }
}

// ---------------------------------------------------------------------------
// fp16 mma.sync GEMM: BM=BN=128, BK=64 per stage, 3-stage cp.async pipeline.
// (Round-14/16 champion config — unchanged.)
// EPI: 0=bias (fp32 C), 1=bias+res (fp32 C), 2=bias+GELU (half C), 3=bias (half C)
// ---------------------------------------------------------------------------
#define SA_STR_H   72
#define SA_H_BYTES (128 * SA_STR_H * 2)      // 18432
#define SB_H_BYTES 16384
#define BUF_H      (SA_H_BYTES + SB_H_BYTES) // 34816
#define GEMM_H_SMEM (3 * BUF_H)              // 104448

template<int EPI>
__global__ void __launch_bounds__(128, 2)
gemm_h_kernel(const __half* __restrict__ A, const uint32_t* __restrict__ Wp,
              const float* __restrict__ bias, const float* __restrict__ res,
              void* __restrict__ Cv, int N, int K)
{
    extern __shared__ char smem[];
    const uint32_t sbase = smem_u32(smem);
    float* Cf = (float*)Cv;
    __half* Ch = (__half*)Cv;

    const int tid  = threadIdx.x;
    const int wid  = tid >> 5;
    const int lane = tid & 31;
    const int g    = lane >> 2;
    const int tig  = lane & 3;
    const int wm   = (wid >> 1) * 64;
    const int wn   = (wid & 1) * 64;
    const int m0   = blockIdx.y * 128;
    const int n0   = blockIdx.x * 128;

    const int ntile = K >> 6;
    const size_t wtile0 = (size_t)blockIdx.x * (K >> 5) * 2048;

    const int am = tid >> 3;
    const int ac = tid & 7;

    const int arow = lane & 15;
    const int acol = (lane >> 4) * 8;

    float acc[4][8][4];
    #pragma unroll
    for (int mt = 0; mt < 4; mt++)
        #pragma unroll
        for (int nb = 0; nb < 8; nb++)
            #pragma unroll
            for (int r = 0; r < 4; r++) acc[mt][nb][r] = 0.f;

    auto load_tile = [&](int buf, int kt) {
        const uint32_t sA = sbase + buf * BUF_H;
        const uint32_t sB = sA + SA_H_BYTES;
        const __half* asrc = A + (size_t)(m0 + am) * K + kt * 64 + ac * 8;
        #pragma unroll
        for (int i = 0; i < 8; i++) {
            CP_ASYNC16(sA + (uint32_t)(am + i * 16) * (SA_STR_H * 2) + ac * 16,
                       asrc + (size_t)i * 16 * K);
        }
        const uint32_t* bsrc = Wp + wtile0 + (size_t)kt * 4096 + tid * 4;
        #pragma unroll
        for (int i = 0; i < 8; i++) {
            CP_ASYNC16(sB + (uint32_t)(tid + i * 128) * 16, bsrc + i * 512);
        }
        CP_COMMIT();
    };

    load_tile(0, 0);
    if (ntile > 1) load_tile(1, 1);

    for (int t = 0; t < ntile; t++) {
        if (t + 1 < ntile) {
            asm volatile("cp.async.wait_group 1;" ::: "memory");
        } else {
            asm volatile("cp.async.wait_group 0;" ::: "memory");
        }
        __syncthreads();
        if (t + 2 < ntile) load_tile((t + 2) % 3, t + 2);

        const int cur = t % 3;
        const uint32_t sA = sbase + cur * BUF_H;
        const uint32_t* Bs = (const uint32_t*)(smem + cur * BUF_H + SA_H_BYTES);

        #pragma unroll
        for (int kbb = 0; kbb < 4; kbb++) {
            uint32_t a[4][4];
            #pragma unroll
            for (int mt = 0; mt < 4; mt++) {
                const uint32_t addr = sA +
                    (uint32_t)((wm + mt * 16 + arow) * SA_STR_H + kbb * 16 + acol) * 2;
                ldsm_x4(a[mt], addr);
            }
            const uint32_t* Bsub = Bs + (kbb >> 1) * 2048;
            #pragma unroll
            for (int nb = 0; nb < 8; nb++) {
                const int s = (kbb & 1) * 16 + (wn >> 3) + nb;
                const uint2 bb = *(const uint2*)(Bsub + s * 64 + lane * 2);
                #pragma unroll
                for (int mt = 0; mt < 4; mt++)
                    mma_f16(acc[mt][nb], a[mt][0], a[mt][1], a[mt][2], a[mt][3],
                            bb.x, bb.y);
            }
        }
    }

    #pragma unroll
    for (int mt = 0; mt < 4; mt++) {
        const size_t r0 = (size_t)(m0 + wm + mt * 16 + g);
        #pragma unroll
        for (int nb = 0; nb < 8; nb++) {
            const int col = n0 + wn + nb * 8 + 2 * tig;
            const float2 bv = *(const float2*)(bias + col);
            #pragma unroll
            for (int hh = 0; hh < 2; hh++) {
                const size_t row = r0 + hh * 8;
                float vx = acc[mt][nb][hh * 2 + 0] + bv.x;
                float vy = acc[mt][nb][hh * 2 + 1] + bv.y;
                if (EPI == 1) {
                    const float2 r2 = *(const float2*)(res + row * N + col);
                    vx += r2.x; vy += r2.y;
                }
                if (EPI == 2) {
                    vx = 0.5f * vx * (1.0f + erff(vx * 0.70710678118654752f));
                    vy = 0.5f * vy * (1.0f + erff(vy * 0.70710678118654752f));
                }
                if (EPI == 2 || EPI == 3) {
                    *(__half2*)(Ch + row * N + col) = __floats2half2_rn(vx, vy);
                } else {
                    float2 o2; o2.x = vx; o2.y = vy;
                    *(float2*)(Cf + row * N + col) = o2;
                }
            }
        }
    }
}

// ---------------------------------------------------------------------------
// LayerNorm: warp-per-row (unchanged)
// ---------------------------------------------------------------------------
__global__ void layernorm_kernel(const float* __restrict__ x,
                                 const float* __restrict__ gamma,
                                 const float* __restrict__ beta,
                                 __half* __restrict__ out)
{
    const int wid  = threadIdx.x >> 5;
    const int lane = threadIdx.x & 31;
    const int row  = blockIdx.x * 8 + wid;

    const float4* xr = (const float4*)(x + (size_t)row * E_);
    float4 v[8];
    float s = 0.f, ss = 0.f;
    #pragma unroll
    for (int i = 0; i < 8; i++) {
        v[i] = xr[lane + 32 * i];
        s  += (v[i].x + v[i].y) + (v[i].z + v[i].w);
        ss += (v[i].x * v[i].x + v[i].y * v[i].y) + (v[i].z * v[i].z + v[i].w * v[i].w);
    }
    #pragma unroll
    for (int o = 16; o > 0; o >>= 1) {
        s  += __shfl_xor_sync(0xffffffffu, s,  o);
        ss += __shfl_xor_sync(0xffffffffu, ss, o);
    }
    const float mean = s * (1.0f / E_);
    const float var  = ss * (1.0f / E_) - mean * mean;
    const float r    = rsqrtf(var + 1e-5f);

    const float4* gp = (const float4*)gamma;
    const float4* bp = (const float4*)beta;
    __half2* op = (__half2*)(out + (size_t)row * E_);
    #pragma unroll
    for (int i = 0; i < 8; i++) {
        const int c4 = lane + 32 * i;
        const float4 gv = gp[c4];
        const float4 bv = bp[c4];
        op[c4 * 2 + 0] = __floats2half2_rn((v[i].x - mean) * r * gv.x + bv.x,
                                           (v[i].y - mean) * r * gv.y + bv.y);
        op[c4 * 2 + 1] = __floats2half2_rn((v[i].z - mean) * r * gv.z + bv.z,
                                           (v[i].w - mean) * r * gv.w + bv.w);
    }
}

// ---------------------------------------------------------------------------
// Flash attention: 64-query blocks, 128 threads, ldmatrix fragments,
// 3-stage K/V ring with a SINGLE __syncthreads per tile.
// smem: Q[64][72] + 3 stages x (K,V)[64][72] = 64512 B; 3 CTAs/SM (reg-bound).
// ---------------------------------------------------------------------------
#define KVSTR 72
#define KVT   (64 * KVSTR)
#define ATT_SMEM (7 * KVT * 2)             // 64512 bytes

__global__ void __launch_bounds__(128, 3)
attn_h_kernel(const __half* __restrict__ qkv, __half* __restrict__ out)
{
    extern __shared__ __half smh[];
    const uint32_t sQ = smem_u32(smh);

    const int bh  = blockIdx.y;
    const int b   = bh >> 4;
    const int h   = bh & 15;
    const int m0  = (gridDim.x - 1 - blockIdx.x) * 64;   // longest blocks first
    const int tid = threadIdx.x;
    const int wid = tid >> 5;
    const int lane = tid & 31;
    const int g    = lane >> 2;
    const int tig  = lane & 3;
    const int qr   = wid * 16;
    const int lq   = lane >> 3;
    const int lr   = lane & 7;
    const float NEG_INF = __int_as_float(0xff800000);

    // ---- stage Q tile (group) + first K/V tile (group) ----
    const size_t baseQ = ((size_t)(b * T_ + m0)) * QKV_N + h * D_;
    #pragma unroll
    for (int i = 0; i < 4; i++) {
        const int idx = tid + i * 128;
        const int r = idx >> 3, c = idx & 7;
        CP_ASYNC16(sQ + (uint32_t)(r * KVSTR + c * 8) * 2,
                   qkv + baseQ + (size_t)r * QKV_N + c * 8);
    }
    CP_COMMIT();

    auto load_kv = [&](int stage, int t) {
        const uint32_t sK = sQ + (uint32_t)(1 + 2 * stage) * (KVT * 2);
        const uint32_t sV = sK + KVT * 2;
        const size_t baseK = ((size_t)(b * T_ + t * 64)) * QKV_N + E_ + h * D_;
        #pragma unroll
        for (int i = 0; i < 4; i++) {
            const int idx = tid + i * 128;
            const int r = idx >> 3, c = idx & 7;
            const __half* src = qkv + baseK + (size_t)r * QKV_N + c * 8;
            CP_ASYNC16(sK + (uint32_t)(r * KVSTR + c * 8) * 2, src);
            CP_ASYNC16(sV + (uint32_t)(r * KVSTR + c * 8) * 2, src + E_);
        }
        CP_COMMIT();
    };
    load_kv(0, 0);

    asm volatile("cp.async.wait_group 0;" ::: "memory");
    __syncthreads();

    // Q fragments, scaled by 2^-3 (exact in fp16)
    const __half2 qscale = __half2half2(__float2half_rn(0.125f));
    uint32_t qf[4][4];
    #pragma unroll
    for (int kc = 0; kc < 4; kc++) {
        const __half* Qp = smh;
        #pragma unroll
        for (int j = 0; j < 4; j++) {
            const int rr = qr + g + (j & 1) * 8;
            const int cc = kc * 16 + 2 * tig + (j >> 1) * 8;
            __half2 q2 = *(const __half2*)(Qp + rr * KVSTR + cc);
            q2 = __hmul2(q2, qscale);
            qf[kc][j] = *(const uint32_t*)&q2;
        }
    }

    float oacc[8][4];
    #pragma unroll
    for (int nb = 0; nb < 8; nb++)
        #pragma unroll
        for (int r = 0; r < 4; r++) oacc[nb][r] = 0.f;
    float mr0 = NEG_INF, mr1 = NEG_INF, l0 = 0.f, l1 = 0.f;

    const int tq0 = m0 + qr + g;
    const int tq1 = tq0 + 8;
    const int ntile = (m0 >> 6) + 1;

    if (ntile > 1) load_kv(1, 1);

    for (int t = 0; t < ntile; t++) {
        const int j0 = t * 64;
        if (t + 1 < ntile) {
            asm volatile("cp.async.wait_group 1;" ::: "memory");
        } else {
            asm volatile("cp.async.wait_group 0;" ::: "memory");
        }
        __syncthreads();                     // single barrier per tile
        if (t + 2 < ntile) load_kv((t + 2) % 3, t + 2);

        const int cur = t % 3;
        const uint32_t sK = sQ + (uint32_t)(1 + 2 * cur) * (KVT * 2);
        const uint32_t sV = sK + KVT * 2;

        // ---- QK^T via ldmatrix K fragments ----
        float sc[8][4];
        #pragma unroll
        for (int jb = 0; jb < 8; jb++)
            sc[jb][0] = sc[jb][1] = sc[jb][2] = sc[jb][3] = 0.f;
        #pragma unroll
        for (int jp = 0; jp < 4; jp++) {
            #pragma unroll
            for (int kc = 0; kc < 4; kc++) {
                uint32_t kb[4];
                const uint32_t addr = sK + (uint32_t)(
                    ((2 * jp + (lq >> 1)) * 8 + lr) * KVSTR + kc * 16 + (lq & 1) * 8) * 2;
                ldsm_x4(kb, addr);
                mma_f16(sc[2 * jp],     qf[kc][0], qf[kc][1], qf[kc][2], qf[kc][3], kb[0], kb[1]);
                mma_f16(sc[2 * jp + 1], qf[kc][0], qf[kc][1], qf[kc][2], qf[kc][3], kb[2], kb[3]);
            }
        }

        // ---- causal mask (diagonal tile only) + row max ----
        if (t == ntile - 1) {
            #pragma unroll
            for (int jb = 0; jb < 8; jb++) {
                const int c0 = j0 + jb * 8 + 2 * tig;
                const int c1 = c0 + 1;
                if (c0 > tq0) sc[jb][0] = NEG_INF;
                if (c1 > tq0) sc[jb][1] = NEG_INF;
                if (c0 > tq1) sc[jb][2] = NEG_INF;
                if (c1 > tq1) sc[jb][3] = NEG_INF;
            }
        }
        float tm0 = NEG_INF, tm1 = NEG_INF;
        #pragma unroll
        for (int jb = 0; jb < 8; jb++) {
            tm0 = fmaxf(tm0, fmaxf(sc[jb][0], sc[jb][1]));
            tm1 = fmaxf(tm1, fmaxf(sc[jb][2], sc[jb][3]));
        }
        tm0 = fmaxf(tm0, __shfl_xor_sync(0xffffffffu, tm0, 1));
        tm0 = fmaxf(tm0, __shfl_xor_sync(0xffffffffu, tm0, 2));
        tm1 = fmaxf(tm1, __shfl_xor_sync(0xffffffffu, tm1, 1));
        tm1 = fmaxf(tm1, __shfl_xor_sync(0xffffffffu, tm1, 2));

        const float mn0 = fmaxf(mr0, tm0);
        const float mn1 = fmaxf(mr1, tm1);
        const float a0 = __expf(mr0 - mn0);
        const float a1 = __expf(mr1 - mn1);
        l0 *= a0; l1 *= a1;
        #pragma unroll
        for (int nb = 0; nb < 8; nb++) {
            oacc[nb][0] *= a0; oacc[nb][1] *= a0;
            oacc[nb][2] *= a1; oacc[nb][3] *= a1;
        }

        // ---- P = exp(S - m) -> A fragments ----
        uint32_t af[4][4];
        float ps0 = 0.f, ps1 = 0.f;
        #pragma unroll
        for (int kc = 0; kc < 4; kc++) {
            const int jA = 2 * kc, jB = 2 * kc + 1;
            const float pA0 = __expf(sc[jA][0] - mn0);
            const float pA1 = __expf(sc[jA][1] - mn0);
            const float pA2 = __expf(sc[jA][2] - mn1);
            const float pA3 = __expf(sc[jA][3] - mn1);
            const float pB0 = __expf(sc[jB][0] - mn0);
            const float pB1 = __expf(sc[jB][1] - mn0);
            const float pB2 = __expf(sc[jB][2] - mn1);
            const float pB3 = __expf(sc[jB][3] - mn1);
            ps0 += (pA0 + pA1) + (pB0 + pB1);
            ps1 += (pA2 + pA3) + (pB2 + pB3);
            af[kc][0] = pack_h2(pA0, pA1);
            af[kc][1] = pack_h2(pA2, pA3);
            af[kc][2] = pack_h2(pB0, pB1);
            af[kc][3] = pack_h2(pB2, pB3);
        }
        ps0 += __shfl_xor_sync(0xffffffffu, ps0, 1);
        ps0 += __shfl_xor_sync(0xffffffffu, ps0, 2);
        ps1 += __shfl_xor_sync(0xffffffffu, ps1, 1);
        ps1 += __shfl_xor_sync(0xffffffffu, ps1, 2);
        l0 += ps0; l1 += ps1;
        mr0 = mn0; mr1 = mn1;

        // ---- PV via ldmatrix.trans V fragments ----
        #pragma unroll
        for (int p = 0; p < 4; p++) {
            #pragma unroll
            for (int kc = 0; kc < 4; kc++) {
                uint32_t vb[4];
                const uint32_t addr = sV + (uint32_t)(
                    (kc * 16 + (lq & 1) * 8 + lr) * KVSTR + p * 16 + (lq >> 1) * 8) * 2;
                ldsm_x4_trans(vb, addr);
                mma_f16(oacc[2 * p],     af[kc][0], af[kc][1], af[kc][2], af[kc][3], vb[0], vb[1]);
                mma_f16(oacc[2 * p + 1], af[kc][0], af[kc][1], af[kc][2], af[kc][3], vb[2], vb[3]);
            }
        }
    }

    // ---- epilogue: normalize, half out ----
    const float inv0 = 1.0f / l0;
    const float inv1 = 1.0f / l1;
    const size_t row0 = (size_t)(b * T_ + tq0);
    const size_t row1 = (size_t)(b * T_ + tq1);
    #pragma unroll
    for (int nb = 0; nb < 8; nb++) {
        const int col = h * D_ + nb * 8 + 2 * tig;
        *(__half2*)(out + row0 * E_ + col) =
            __floats2half2_rn(oacc[nb][0] * inv0, oacc[nb][1] * inv0);
        *(__half2*)(out + row1 * E_ + col) =
            __floats2half2_rn(oacc[nb][2] * inv1, oacc[nb][3] * inv1);
    }
}

// ---------------------------------------------------------------------------
// Launch (stream fork/join for packs, unchanged from Round 16)
// ---------------------------------------------------------------------------
extern "C" void kernel_launch(void* const* d_in, const int* in_sizes, int n_in,
                              void* d_out, int out_size)
{
    const float* x      = (const float*)d_in[0];
    const float* ln1_g  = (const float*)d_in[1];
    const float* ln1_b  = (const float*)d_in[2];
    const float* ln2_g  = (const float*)d_in[3];
    const float* ln2_b  = (const float*)d_in[4];
    const float* W_qkv  = (const float*)d_in[5];
    const float* b_qkv  = (const float*)d_in[6];
    const float* W_o    = (const float*)d_in[7];
    const float* b_o    = (const float*)d_in[8];
    const float* W_fc   = (const float*)d_in[9];
    const float* b_fc   = (const float*)d_in[10];
    const float* W_proj = (const float*)d_in[11];
    const float* b_proj = (const float*)d_in[12];
    float* out = (float*)d_out;

    __half *p_lnH, *p_qkvH, *p_attnH, *p_fcH;
    float *p_x1;
    uint32_t *p_wqkvP, *p_woP, *p_wfcP, *p_wprojP;
    cudaGetSymbolAddress((void**)&p_lnH,    g_lnH);
    cudaGetSymbolAddress((void**)&p_qkvH,   g_qkvH);
    cudaGetSymbolAddress((void**)&p_attnH,  g_attnH);
    cudaGetSymbolAddress((void**)&p_x1,     g_x1);
    cudaGetSymbolAddress((void**)&p_fcH,    g_fcH);
    cudaGetSymbolAddress((void**)&p_wqkvP,  g_wqkvP);
    cudaGetSymbolAddress((void**)&p_woP,    g_woP);
    cudaGetSymbolAddress((void**)&p_wfcP,   g_wfcP);
    cudaGetSymbolAddress((void**)&p_wprojP, g_wprojP);

    cudaFuncSetAttribute(gemm_h_kernel<0>, cudaFuncAttributeMaxDynamicSharedMemorySize, GEMM_H_SMEM);
    cudaFuncSetAttribute(gemm_h_kernel<1>, cudaFuncAttributeMaxDynamicSharedMemorySize, GEMM_H_SMEM);
    cudaFuncSetAttribute(gemm_h_kernel<2>, cudaFuncAttributeMaxDynamicSharedMemorySize, GEMM_H_SMEM);
    cudaFuncSetAttribute(gemm_h_kernel<3>, cudaFuncAttributeMaxDynamicSharedMemorySize, GEMM_H_SMEM);
    cudaFuncSetAttribute(attn_h_kernel,    cudaFuncAttributeMaxDynamicSharedMemorySize, ATT_SMEM);

    cudaStream_t s2;
    cudaStreamCreateWithFlags(&s2, cudaStreamNonBlocking);
    cudaEvent_t evFork, evJoin;
    cudaEventCreateWithFlags(&evFork, cudaEventDisableTiming);
    cudaEventCreateWithFlags(&evJoin, cudaEventDisableTiming);

    // 0a. qkv pack (critical path) on main stream
    pack_all_kernel<<<768, 256>>>(W_qkv, p_wqkvP, W_o, p_woP, W_fc, p_wfcP, W_proj, p_wprojP, 0);

    // fork: remaining packs overlap LN1 + qkv GEMM + attention
    cudaEventRecord(evFork, 0);
    cudaStreamWaitEvent(s2, evFork, 0);
    pack_all_kernel<<<2304, 256, 0, s2>>>(W_qkv, p_wqkvP, W_o, p_woP, W_fc, p_wfcP, W_proj, p_wprojP, 768);
    cudaEventRecord(evJoin, s2);

    // 1. ln1 = LN(x) -> half
    layernorm_kernel<<<M_ / 8, 256>>>(x, ln1_g, ln1_b, p_lnH);
    // 2. qkv = ln1 @ W_qkv + b_qkv -> half
    gemm_h_kernel<3><<<dim3(QKV_N / 128, M_ / 128), 128, GEMM_H_SMEM>>>(
        p_lnH, p_wqkvP, b_qkv, nullptr, p_qkvH, QKV_N, E_);
    // 3. attention
    attn_h_kernel<<<dim3(T_ / 64, B_ * H_), 128, ATT_SMEM>>>(p_qkvH, p_attnH);

    // join
    cudaStreamWaitEvent(0, evJoin, 0);

    // 4. x1 = x + attn @ W_o + b_o (fp32 out)
    gemm_h_kernel<1><<<dim3(E_ / 128, M_ / 128), 128, GEMM_H_SMEM>>>(
        p_attnH, p_woP, b_o, x, p_x1, E_, E_);
    // 5. ln2 = LN(x1) -> half
    layernorm_kernel<<<M_ / 8, 256>>>(p_x1, ln2_g, ln2_b, p_lnH);
    // 6. fc = gelu(ln2 @ W_fc + b_fc) -> half
    gemm_h_kernel<2><<<dim3(FC_N / 128, M_ / 128), 128, GEMM_H_SMEM>>>(
        p_lnH, p_wfcP, b_fc, nullptr, p_fcH, FC_N, E_);
    // 7. out = x1 + fc @ W_proj + b_proj (fp32 out)
    gemm_h_kernel<1><<<dim3(E_ / 128, M_ / 128), 128, GEMM_H_SMEM>>>(
        p_fcH, p_wprojP, b_proj, p_x1, out, E_, FC_N);
}